// round 1
// baseline (speedup 1.0000x reference)
#include <cuda_runtime.h>
#include <mma.h>

using namespace nvcuda;

#define NEXP 16
#define TTOT 8192
#define DM   1024
#define DF   2048
#define TPE  TTOT

#define BM 128
#define BN 128
#define BK 32
#define LDA_S 40
#define SMEM_FLOATS (2*BM*LDA_S + 2*BK*BN)
#define SMEM_BYTES  (SMEM_FLOATS*4)

// ---------------- device scratch (no allocations allowed) ----------------
__device__ int   g_cnt[NEXP];
__device__ int   g_off[NEXP];
__device__ int   g_tok[NEXP*TPE];
__device__ float g_wt [NEXP*TPE];
__device__ float g_G  [(size_t)2*TTOT*DF];   // gate projections (compact rows)
__device__ float g_ACT[(size_t)2*TTOT*DF];   // silu(G)*U       (compact rows)

// ---------------- small kernels ----------------
__global__ void zero_cnt_kernel(){
    if (threadIdx.x < NEXP) g_cnt[threadIdx.x] = 0;
}

__global__ void scan_kernel(){
    if (threadIdx.x == 0){
        int s = 0;
        #pragma unroll
        for (int e = 0; e < NEXP; e++){ g_off[e] = s; s += g_cnt[e]; }
    }
}

// one warp per token: logits -> softmax -> top2 -> renormalize -> expert lists
__global__ void router_kernel(const float* __restrict__ x, const float* __restrict__ Wr){
    int gw   = (blockIdx.x*blockDim.x + threadIdx.x) >> 5;
    int lane = threadIdx.x & 31;
    if (gw >= TTOT) return;
    const float* xr = x + (size_t)gw * DM;
    float acc[NEXP];
    #pragma unroll
    for (int e = 0; e < NEXP; e++) acc[e] = 0.f;
    for (int d = lane; d < DM; d += 32){
        float xv = xr[d];
        const float4* wr = reinterpret_cast<const float4*>(Wr + d*NEXP);
        #pragma unroll
        for (int q = 0; q < 4; q++){
            float4 w = wr[q];
            acc[4*q+0] = fmaf(xv, w.x, acc[4*q+0]);
            acc[4*q+1] = fmaf(xv, w.y, acc[4*q+1]);
            acc[4*q+2] = fmaf(xv, w.z, acc[4*q+2]);
            acc[4*q+3] = fmaf(xv, w.w, acc[4*q+3]);
        }
    }
    #pragma unroll
    for (int e = 0; e < NEXP; e++){
        #pragma unroll
        for (int o = 16; o > 0; o >>= 1) acc[e] += __shfl_xor_sync(0xffffffffu, acc[e], o);
    }
    if (lane == 0){
        float mx = acc[0];
        #pragma unroll
        for (int e = 1; e < NEXP; e++) mx = fmaxf(mx, acc[e]);
        float p[NEXP];
        #pragma unroll
        for (int e = 0; e < NEXP; e++) p[e] = __expf(acc[e] - mx);
        float b1 = -1.f, b2 = -1.f; int i1 = 0, i2 = 0;
        #pragma unroll
        for (int e = 0; e < NEXP; e++){
            float v = p[e];
            if (v > b1){ b2 = b1; i2 = i1; b1 = v; i1 = e; }
            else if (v > b2){ b2 = v; i2 = e; }
        }
        float inv = 1.f / (b1 + b2);
        int pos1 = atomicAdd(&g_cnt[i1], 1);
        g_tok[i1*TPE + pos1] = gw;  g_wt[i1*TPE + pos1] = b1 * inv;
        int pos2 = atomicAdd(&g_cnt[i2], 1);
        g_tok[i2*TPE + pos2] = gw;  g_wt[i2*TPE + pos2] = b2 * inv;
    }
}

// ---------------- TF32 tiled GEMM ----------------
// MODE 0: dense A=x,      C -> g_G[row]                 (shared gate)
// MODE 1: dense A=x,      C -> g_ACT = silu(g_G)*C      (shared up)
// MODE 2: dense A=g_ACT,  C -> Out (plain store)        (shared down)
// MODE 3: gathered A=x,   C -> g_G[off+row]             (routed gate)
// MODE 4: gathered A=x,   C -> g_ACT = silu(g_G)*C      (routed up)
// MODE 5: A=g_ACT segment, Out += w * C  (atomic)       (routed down)

__device__ __forceinline__ void cp_async16(unsigned saddr, const void* gptr, int szbytes){
    asm volatile("cp.async.ca.shared.global [%0], [%1], 16, %2;\n"
                 :: "r"(saddr), "l"(gptr), "r"(szbytes) : "memory");
}
__device__ __forceinline__ void cp_commit(){ asm volatile("cp.async.commit_group;\n" ::: "memory"); }
__device__ __forceinline__ void cp_wait1(){ asm volatile("cp.async.wait_group 1;\n" ::: "memory"); }

template <class Frag>
__device__ __forceinline__ void to_tf32(Frag& f){
    #pragma unroll
    for (int t = 0; t < f.num_elements; t++) f.x[t] = wmma::__float_to_tf32(f.x[t]);
}

template<int MODE>
__global__ void __launch_bounds__(256)
gemm_kernel(const float* __restrict__ Ain, const float* __restrict__ Bbase,
            long strideB, int K, int N, int M_dense, float* __restrict__ Out)
{
    extern __shared__ float sm[];
    float* As = sm;                     // [2][BM*LDA_S]
    float* Bs = sm + 2*BM*LDA_S;        // [2][BK*BN]

    const int e  = blockIdx.z;
    const int M  = (MODE >= 3) ? g_cnt[e] : M_dense;
    const int m0 = blockIdx.y * BM;
    if (m0 >= M) return;
    const int n0 = blockIdx.x * BN;

    const float* A = (MODE == 2 || MODE == 5) ? (const float*)g_ACT : Ain;
    const float* B = Bbase + (size_t)e * strideB;
    const int offe = (MODE >= 3) ? g_off[e] : 0;

    const int tid = threadIdx.x;
    const int ar = tid >> 3,  ac = (tid & 7)  * 4;
    const int br = tid >> 5,  bc = (tid & 31) * 4;

    // A row pointers for the 4 rows this thread loads per stage
    const float* arow[4];
    int aval[4];
    #pragma unroll
    for (int p = 0; p < 4; p++){
        int gm = m0 + ar + p*32;
        int v  = (gm < M);
        long grow;
        if (MODE == 3 || MODE == 4) grow = v ? g_tok[e*TPE + gm] : 0;
        else if (MODE == 5)         grow = v ? (long)(offe + gm) : 0;
        else                        grow = v ? gm : 0;
        arow[p] = A + (size_t)grow * K;
        aval[p] = v ? 16 : 0;
    }

    const int warpId = tid >> 5;
    const int wm = warpId >> 2;   // 0..1 (64 rows each)
    const int wn = warpId & 3;    // 0..3 (32 cols each)

    wmma::fragment<wmma::accumulator, 16, 16, 8, float> c[4][2];
    #pragma unroll
    for (int i = 0; i < 4; i++)
        #pragma unroll
        for (int j = 0; j < 2; j++) wmma::fill_fragment(c[i][j], 0.f);

    const int KT = K / BK;

    // stage loaders
    auto loadA = [&](int s, int kt){
        float* dst0 = As + s*BM*LDA_S;
        int k0 = kt * BK;
        #pragma unroll
        for (int p = 0; p < 4; p++){
            int r = ar + p*32;
            unsigned saddr = (unsigned)__cvta_generic_to_shared(dst0 + r*LDA_S + ac);
            cp_async16(saddr, arow[p] + k0 + ac, aval[p]);
        }
    };
    auto loadB = [&](int s, int kt){
        float* dst0 = Bs + s*BK*BN;
        int k0 = kt * BK;
        #pragma unroll
        for (int p = 0; p < 4; p++){
            int r = br + p*8;
            unsigned saddr = (unsigned)__cvta_generic_to_shared(dst0 + r*BN + bc);
            cp_async16(saddr, B + (size_t)(k0 + r)*N + n0 + bc, 16);
        }
    };

    loadA(0, 0); loadB(0, 0);
    cp_commit();

    for (int kt = 0; kt < KT; kt++){
        int s = kt & 1;
        if (kt + 1 < KT){ loadA(s ^ 1, kt + 1); loadB(s ^ 1, kt + 1); }
        cp_commit();
        cp_wait1();
        __syncthreads();

        const float* a0 = As + s*BM*LDA_S;
        const float* b0 = Bs + s*BK*BN;
        #pragma unroll
        for (int kk = 0; kk < BK; kk += 8){
            wmma::fragment<wmma::matrix_a, 16, 16, 8, wmma::precision::tf32, wmma::row_major> a[4];
            wmma::fragment<wmma::matrix_b, 16, 16, 8, wmma::precision::tf32, wmma::row_major> b[2];
            #pragma unroll
            for (int i = 0; i < 4; i++){
                wmma::load_matrix_sync(a[i], a0 + (size_t)(wm*64 + i*16)*LDA_S + kk, LDA_S);
                to_tf32(a[i]);
            }
            #pragma unroll
            for (int j = 0; j < 2; j++){
                wmma::load_matrix_sync(b[j], b0 + (size_t)kk*BN + wn*32 + j*16, BN);
                to_tf32(b[j]);
            }
            #pragma unroll
            for (int i = 0; i < 4; i++)
                #pragma unroll
                for (int j = 0; j < 2; j++)
                    wmma::mma_sync(c[i][j], a[i], b[j], c[i][j]);
        }
        __syncthreads();
    }

    // ---------------- epilogue: stage C tile in smem (reuse A/B buffers) ----------------
    float* Cs = sm;  // 128*128 floats = 64KB <= 72KB
    __syncthreads();
    #pragma unroll
    for (int i = 0; i < 4; i++)
        #pragma unroll
        for (int j = 0; j < 2; j++)
            wmma::store_matrix_sync(Cs + (size_t)(wm*64 + i*16)*BN + wn*32 + j*16,
                                    c[i][j], BN, wmma::mem_row_major);
    __syncthreads();

    #pragma unroll
    for (int it = 0; it < 16; it++){
        int idx = tid + it*256;            // float4 index, 4096 total
        int r   = idx >> 5;
        int cc  = (idx & 31) * 4;
        int gm  = m0 + r;
        if (gm >= M) continue;
        float4 v = *reinterpret_cast<float4*>(Cs + (size_t)r*BN + cc);

        if (MODE == 0 || MODE == 3){
            size_t row = (size_t)(offe + gm);
            *reinterpret_cast<float4*>(g_G + row*N + n0 + cc) = v;
        } else if (MODE == 1 || MODE == 4){
            size_t row = (size_t)(offe + gm);
            float4 g4 = *reinterpret_cast<const float4*>(g_G + row*N + n0 + cc);
            float4 o;
            o.x = v.x * (g4.x / (1.f + __expf(-g4.x)));
            o.y = v.y * (g4.y / (1.f + __expf(-g4.y)));
            o.z = v.z * (g4.z / (1.f + __expf(-g4.z)));
            o.w = v.w * (g4.w / (1.f + __expf(-g4.w)));
            *reinterpret_cast<float4*>(g_ACT + row*N + n0 + cc) = o;
        } else if (MODE == 2){
            *reinterpret_cast<float4*>(Out + (size_t)gm*N + n0 + cc) = v;
        } else { // MODE 5: weighted scatter-add to token rows
            int   t = g_tok[e*TPE + gm];
            float w = g_wt [e*TPE + gm];
            float* op = Out + (size_t)t*N + n0 + cc;
            atomicAdd(op + 0, w * v.x);
            atomicAdd(op + 1, w * v.y);
            atomicAdd(op + 2, w * v.z);
            atomicAdd(op + 3, w * v.w);
        }
    }
}

// ---------------- launch ----------------
extern "C" void kernel_launch(void* const* d_in, const int* in_sizes, int n_in,
                              void* d_out, int out_size)
{
    const float* x   = (const float*)d_in[0];
    const float* Wr  = (const float*)d_in[1];
    const float* Wsg = (const float*)d_in[2];
    const float* Wsu = (const float*)d_in[3];
    const float* Wsd = (const float*)d_in[4];
    const float* Weg = (const float*)d_in[5];
    const float* Weu = (const float*)d_in[6];
    const float* Wed = (const float*)d_in[7];
    float* out = (float*)d_out;

    cudaFuncSetAttribute(gemm_kernel<0>, cudaFuncAttributeMaxDynamicSharedMemorySize, SMEM_BYTES);
    cudaFuncSetAttribute(gemm_kernel<1>, cudaFuncAttributeMaxDynamicSharedMemorySize, SMEM_BYTES);
    cudaFuncSetAttribute(gemm_kernel<2>, cudaFuncAttributeMaxDynamicSharedMemorySize, SMEM_BYTES);
    cudaFuncSetAttribute(gemm_kernel<3>, cudaFuncAttributeMaxDynamicSharedMemorySize, SMEM_BYTES);
    cudaFuncSetAttribute(gemm_kernel<4>, cudaFuncAttributeMaxDynamicSharedMemorySize, SMEM_BYTES);
    cudaFuncSetAttribute(gemm_kernel<5>, cudaFuncAttributeMaxDynamicSharedMemorySize, SMEM_BYTES);

    dim3 blk(256);

    // router + expert lists
    zero_cnt_kernel<<<1, 32>>>();
    router_kernel<<<TTOT/8, 256>>>(x, Wr);
    scan_kernel<<<1, 32>>>();

    const long sGU = (long)DM * DF;   // per-expert stride for gate/up weights
    const long sD  = (long)DF * DM;   // per-expert stride for down weights

    // shared expert (dense, rows 0..TTOT of scratch)
    gemm_kernel<0><<<dim3(DF/BN, TTOT/BM, 1), blk, SMEM_BYTES>>>(x,      Wsg, 0, DM, DF, TTOT, nullptr);
    gemm_kernel<1><<<dim3(DF/BN, TTOT/BM, 1), blk, SMEM_BYTES>>>(x,      Wsu, 0, DM, DF, TTOT, nullptr);
    gemm_kernel<2><<<dim3(DM/BN, TTOT/BM, 1), blk, SMEM_BYTES>>>(nullptr, Wsd, 0, DF, DM, TTOT, out);

    // routed experts (gathered rows, compact scratch offsets)
    gemm_kernel<3><<<dim3(DF/BN, TPE/BM, NEXP), blk, SMEM_BYTES>>>(x,      Weg, sGU, DM, DF, 0, nullptr);
    gemm_kernel<4><<<dim3(DF/BN, TPE/BM, NEXP), blk, SMEM_BYTES>>>(x,      Weu, sGU, DM, DF, 0, nullptr);
    gemm_kernel<5><<<dim3(DM/BN, TPE/BM, NEXP), blk, SMEM_BYTES>>>(nullptr, Wed, sD,  DF, DM, 0, out);
}

// round 4
// speedup vs baseline: 2.3728x; 2.3728x over previous
#include <cuda_runtime.h>
#include <cstdint>

#define NEXP 16
#define TTOT 8192
#define DM   1024
#define DF   2048
#define TPE  TTOT

#define BM   128     // CTA M tile
#define BN   128     // CTA N tile
#define BKC  32      // K chunk
#define AST  36      // A smem row stride (floats) -> conflict-free
#define BST  136     // B smem row stride (floats) -> conflict-free
#define ASZ  (BM*AST)       // 4608 floats
#define BSZ  (BKC*BST)      // 4352 floats
#define STG  (ASZ+BSZ)      // 8960 floats per stage
#define SMEM_BYTES (2*STG*4) // 71680 B

// ---------------- device scratch (static; no allocations) ----------------
__device__ int   g_cnt[NEXP];
__device__ int   g_off[NEXP];
__device__ int   g_tok[NEXP*TPE];
__device__ float g_wt [NEXP*TPE];
__device__ float g_Xr [(size_t)TTOT*DM];            // RNA-rounded x
__device__ float g_G  [(size_t)2*TTOT*DF];          // gate projections (compact rows)
__device__ float g_ACT[(size_t)3*TTOT*DF];          // dense rows [0,T), routed rows [T,3T)

// ---------------- helpers ----------------
__device__ __forceinline__ float tf32rnd(float v){
    uint32_t o; asm("cvt.rna.tf32.f32 %0, %1;" : "=r"(o) : "f"(v));
    return __uint_as_float(o);
}
__device__ __forceinline__ void cp_async16(uint32_t saddr, const void* g, int sz){
    asm volatile("cp.async.ca.shared.global [%0], [%1], 16, %2;\n" :: "r"(saddr), "l"(g), "r"(sz) : "memory");
}
__device__ __forceinline__ void cp_commit(){ asm volatile("cp.async.commit_group;\n" ::: "memory"); }
__device__ __forceinline__ void cp_wait1(){ asm volatile("cp.async.wait_group 1;\n" ::: "memory"); }
__device__ __forceinline__ void cp_wait0(){ asm volatile("cp.async.wait_group 0;\n" ::: "memory"); }
__device__ __forceinline__ uint32_t smem_u32(const void* p){
    uint32_t a;
    asm("{ .reg .u64 t; cvta.to.shared.u64 t, %1; cvt.u32.u64 %0, t; }" : "=r"(a) : "l"(p));
    return a;
}

// mma.sync m16n8k8 tf32: D = A*B + C   (A row-major 16x8, B col-major 8x8)
__device__ __forceinline__ void mma_tf32(float c[4], uint32_t a0, uint32_t a1, uint32_t a2, uint32_t a3,
                                         uint32_t b0, uint32_t b1){
    asm volatile("mma.sync.aligned.m16n8k8.row.col.f32.tf32.tf32.f32 "
                 "{%0,%1,%2,%3}, {%4,%5,%6,%7}, {%8,%9}, {%0,%1,%2,%3};"
                 : "+f"(c[0]), "+f"(c[1]), "+f"(c[2]), "+f"(c[3])
                 : "r"(a0), "r"(a1), "r"(a2), "r"(a3), "r"(b0), "r"(b1));
}

// ---------------- small kernels ----------------
__global__ void zero_cnt_kernel(){ if (threadIdx.x < NEXP) g_cnt[threadIdx.x] = 0; }

__global__ void scan_kernel(){
    if (threadIdx.x == 0){
        int s = 0;
        #pragma unroll
        for (int e = 0; e < NEXP; e++){ g_off[e] = s; s += g_cnt[e]; }
    }
}

__global__ void roundx_kernel(const float* __restrict__ x){
    int i = blockIdx.x*blockDim.x + threadIdx.x;
    float4 v = reinterpret_cast<const float4*>(x)[i];
    v.x = tf32rnd(v.x); v.y = tf32rnd(v.y); v.z = tf32rnd(v.z); v.w = tf32rnd(v.w);
    reinterpret_cast<float4*>(g_Xr)[i] = v;
}

// router: one warp per token (validated in R1)
__global__ void router_kernel(const float* __restrict__ x, const float* __restrict__ Wr){
    int gw   = (blockIdx.x*blockDim.x + threadIdx.x) >> 5;
    int lane = threadIdx.x & 31;
    if (gw >= TTOT) return;
    const float* xr = x + (size_t)gw * DM;
    float acc[NEXP];
    #pragma unroll
    for (int e = 0; e < NEXP; e++) acc[e] = 0.f;
    for (int d = lane; d < DM; d += 32){
        float xv = xr[d];
        const float4* wr = reinterpret_cast<const float4*>(Wr + d*NEXP);
        #pragma unroll
        for (int q = 0; q < 4; q++){
            float4 w = wr[q];
            acc[4*q+0] = fmaf(xv, w.x, acc[4*q+0]);
            acc[4*q+1] = fmaf(xv, w.y, acc[4*q+1]);
            acc[4*q+2] = fmaf(xv, w.z, acc[4*q+2]);
            acc[4*q+3] = fmaf(xv, w.w, acc[4*q+3]);
        }
    }
    #pragma unroll
    for (int e = 0; e < NEXP; e++){
        #pragma unroll
        for (int o = 16; o > 0; o >>= 1) acc[e] += __shfl_xor_sync(0xffffffffu, acc[e], o);
    }
    if (lane == 0){
        float mx = acc[0];
        #pragma unroll
        for (int e = 1; e < NEXP; e++) mx = fmaxf(mx, acc[e]);
        float p[NEXP];
        #pragma unroll
        for (int e = 0; e < NEXP; e++) p[e] = __expf(acc[e] - mx);
        float b1 = -1.f, b2 = -1.f; int i1 = 0, i2 = 0;
        #pragma unroll
        for (int e = 0; e < NEXP; e++){
            float v = p[e];
            if (v > b1){ b2 = b1; i2 = i1; b1 = v; i1 = e; }
            else if (v > b2){ b2 = v; i2 = e; }
        }
        float inv = 1.f / (b1 + b2);
        int p1 = atomicAdd(&g_cnt[i1], 1);
        g_tok[i1*TPE + p1] = gw;  g_wt[i1*TPE + p1] = b1 * inv;
        int p2 = atomicAdd(&g_cnt[i2], 1);
        g_tok[i2*TPE + p2] = gw;  g_wt[i2*TPE + p2] = b2 * inv;
    }
}

// ---------------- tf32 mma.sync GEMM ----------------
// MODE 0: dense  A=g_Xr      B=Wsg       -> g_G
// MODE 1: dense  A=g_Xr      B=Wsu       -> g_ACT = silu(g_G)*C
// MODE 2: dense  A=g_ACT     B=Wsd       -> Out (plain store)
// MODE 3: routed A=gather(Xr) B=Weg[e]   -> g_G[off+row]
// MODE 4: routed A=gather(Xr) B=Weu[e]   -> g_ACT[T+off+row] = silu(g_G)*C
// MODE 5: routed A=g_ACT seg B=Wed[e]    -> Out += w * C (atomic)
// A pointers are resolved DEVICE-SIDE (device globals are not valid host args).

template<int MODE>
__global__ void __launch_bounds__(256)
mma_kernel(const float* __restrict__ Bbase, float* __restrict__ Out)
{
    constexpr int K   = (MODE==2 || MODE==5) ? DF : DM;
    constexpr int LDB = (MODE==2 || MODE==5) ? DM : DF;
    constexpr int KT  = K / BKC;
    extern __shared__ float sm[];

    const int e  = (MODE >= 3) ? blockIdx.z : 0;
    const int M  = (MODE >= 3) ? g_cnt[e] : TTOT;
    const int m0 = blockIdx.y * BM;
    if (m0 >= M) return;
    const int n0 = blockIdx.x * BN;

    const float* B = Bbase + (size_t)e * ((size_t)K * LDB);
    const int offe = (MODE >= 3) ? g_off[e] : 0;

    // device-side A selection (fix for R3: g_Xr/g_ACT must not come from host)
    const float* A;
    if      (MODE == 2) A = g_ACT;
    else if (MODE == 5) A = g_ACT + (size_t)(TTOT + offe) * DF;
    else                A = g_Xr;

    const int tid = threadIdx.x;

    // ---- A stage loaders: 4 rows/thread (rb + p*32), 4 floats each
    const int rb  = tid >> 3;
    const int cfa = (tid & 7) * 4;
    const float* arow[4]; int asz[4];
    #pragma unroll
    for (int p = 0; p < 4; p++){
        int gm = m0 + rb + p*32;
        if (MODE == 3 || MODE == 4){
            int ok = gm < M;
            arow[p] = A + (size_t)(ok ? g_tok[e*TPE + gm] : 0) * DM;
            asz[p]  = ok ? 16 : 0;
        } else if (MODE == 5){
            int ok = gm < M;
            arow[p] = A + (size_t)(ok ? gm : 0) * DF;
            asz[p]  = ok ? 16 : 0;
        } else {
            arow[p] = A + (size_t)gm * K;
            asz[p]  = 16;
        }
    }
    // ---- B stage loaders: rows rb2 + p*8 of the 32xBN chunk
    const int rb2 = tid >> 5;
    const int cfb = (tid & 31) * 4;

    const uint32_t smb = smem_u32(sm);

    auto load_chunk = [&](int kt, int s){
        const int k0 = kt * BKC;
        #pragma unroll
        for (int p = 0; p < 4; p++){
            uint32_t d = smb + (uint32_t)(( (size_t)(s*STG) + (rb + p*32)*AST + cfa) * 4);
            cp_async16(d, arow[p] + k0 + cfa, asz[p]);
        }
        #pragma unroll
        for (int p = 0; p < 4; p++){
            int r = rb2 + p*8;
            uint32_t d = smb + (uint32_t)(( (size_t)(s*STG) + ASZ + r*BST + cfb) * 4);
            cp_async16(d, B + (size_t)(k0 + r)*LDB + n0 + cfb, 16);
        }
    };

    // round B chunk to tf32 (RNA) in-place: each thread rounds the float4s it staged
    auto round_B = [&](int s){
        float* Bs0 = sm + s*STG + ASZ;
        #pragma unroll
        for (int p = 0; p < 4; p++){
            float4* q = reinterpret_cast<float4*>(Bs0 + (rb2 + p*8)*BST + cfb);
            float4 v = *q;
            v.x = tf32rnd(v.x); v.y = tf32rnd(v.y); v.z = tf32rnd(v.z); v.w = tf32rnd(v.w);
            *q = v;
        }
    };

    // ---- fragment accumulators: warp tile 64x32
    const int wid = tid >> 5, lane = tid & 31;
    const int g = lane >> 2, t = lane & 3;
    const int wm = wid & 1;        // 2 m-blocks of 64
    const int wn = wid >> 1;       // 4 n-blocks of 32
    float c[4][4][4];
    #pragma unroll
    for (int i = 0; i < 4; i++)
        #pragma unroll
        for (int j = 0; j < 4; j++)
            #pragma unroll
            for (int q = 0; q < 4; q++) c[i][j][q] = 0.f;

    load_chunk(0, 0); cp_commit();

    for (int kt = 0; kt < KT; kt++){
        const int s = kt & 1;
        if (kt + 1 < KT){ load_chunk(kt+1, s^1); cp_commit(); cp_wait1(); }
        else            { cp_wait0(); }
        round_B(s);
        __syncthreads();

        const float* As0 = sm + s*STG;
        const float* Bs0 = As0 + ASZ;
        const float* ab = As0 + (wm*64 + g)*AST + t;
        const float* bb = Bs0 + t*BST + wn*32 + g;

        #pragma unroll
        for (int kk = 0; kk < BKC; kk += 8){
            uint32_t a[4][4], b[4][2];
            #pragma unroll
            for (int i = 0; i < 4; i++){
                a[i][0] = __float_as_uint(ab[(i*16    )*AST + kk    ]);
                a[i][1] = __float_as_uint(ab[(i*16 + 8)*AST + kk    ]);
                a[i][2] = __float_as_uint(ab[(i*16    )*AST + kk + 4]);
                a[i][3] = __float_as_uint(ab[(i*16 + 8)*AST + kk + 4]);
            }
            #pragma unroll
            for (int j = 0; j < 4; j++){
                b[j][0] = __float_as_uint(bb[(kk    )*BST + j*8]);
                b[j][1] = __float_as_uint(bb[(kk + 4)*BST + j*8]);
            }
            #pragma unroll
            for (int i = 0; i < 4; i++)
                #pragma unroll
                for (int j = 0; j < 4; j++)
                    mma_tf32(c[i][j], a[i][0], a[i][1], a[i][2], a[i][3], b[j][0], b[j][1]);
        }
        __syncthreads();
    }

    // ---- register epilogue: c[i][j] maps to rows (g,g+8)+i*16+wm*64, cols wn*32+j*8+2t(+1)
    #pragma unroll
    for (int i = 0; i < 4; i++){
        #pragma unroll
        for (int h = 0; h < 2; h++){
            const int gm = m0 + wm*64 + i*16 + g + h*8;
            if ((MODE >= 3) && gm >= M) continue;
            #pragma unroll
            for (int j = 0; j < 4; j++){
                const int cc = n0 + wn*32 + j*8 + 2*t;
                const float v0 = c[i][j][2*h + 0];
                const float v1 = c[i][j][2*h + 1];
                if (MODE == 0 || MODE == 3){
                    float2* dst = reinterpret_cast<float2*>(g_G + (size_t)(offe + gm)*DF + cc);
                    *dst = make_float2(v0, v1);
                } else if (MODE == 1 || MODE == 4){
                    const float2 gg = *reinterpret_cast<const float2*>(g_G + (size_t)(offe + gm)*DF + cc);
                    const int abase = (MODE == 4) ? (TTOT + offe) : 0;
                    float2* dst = reinterpret_cast<float2*>(g_ACT + (size_t)(abase + gm)*DF + cc);
                    float o0 = tf32rnd(v0 * (gg.x / (1.f + __expf(-gg.x))));
                    float o1 = tf32rnd(v1 * (gg.y / (1.f + __expf(-gg.y))));
                    *dst = make_float2(o0, o1);
                } else if (MODE == 2){
                    float2* dst = reinterpret_cast<float2*>(Out + (size_t)gm*DM + cc);
                    *dst = make_float2(v0, v1);
                } else { // MODE 5
                    const int   tok = g_tok[e*TPE + gm];
                    const float w   = g_wt [e*TPE + gm];
                    float* dst = Out + (size_t)tok*DM + cc;
                    atomicAdd(dst + 0, w * v0);
                    atomicAdd(dst + 1, w * v1);
                }
            }
        }
    }
}

// ---------------- launch ----------------
extern "C" void kernel_launch(void* const* d_in, const int* in_sizes, int n_in,
                              void* d_out, int out_size)
{
    const float* x   = (const float*)d_in[0];
    const float* Wr  = (const float*)d_in[1];
    const float* Wsg = (const float*)d_in[2];
    const float* Wsu = (const float*)d_in[3];
    const float* Wsd = (const float*)d_in[4];
    const float* Weg = (const float*)d_in[5];
    const float* Weu = (const float*)d_in[6];
    const float* Wed = (const float*)d_in[7];
    float* out = (float*)d_out;

    cudaFuncSetAttribute(mma_kernel<0>, cudaFuncAttributeMaxDynamicSharedMemorySize, SMEM_BYTES);
    cudaFuncSetAttribute(mma_kernel<1>, cudaFuncAttributeMaxDynamicSharedMemorySize, SMEM_BYTES);
    cudaFuncSetAttribute(mma_kernel<2>, cudaFuncAttributeMaxDynamicSharedMemorySize, SMEM_BYTES);
    cudaFuncSetAttribute(mma_kernel<3>, cudaFuncAttributeMaxDynamicSharedMemorySize, SMEM_BYTES);
    cudaFuncSetAttribute(mma_kernel<4>, cudaFuncAttributeMaxDynamicSharedMemorySize, SMEM_BYTES);
    cudaFuncSetAttribute(mma_kernel<5>, cudaFuncAttributeMaxDynamicSharedMemorySize, SMEM_BYTES);

    // router + expert lists + rounded activations
    zero_cnt_kernel<<<1, 32>>>();
    router_kernel<<<TTOT/8, 256>>>(x, Wr);
    scan_kernel<<<1, 32>>>();
    roundx_kernel<<<(TTOT*DM/4)/256, 256>>>(x);

    dim3 blk(256);
    // shared expert
    mma_kernel<0><<<dim3(DF/BN, TTOT/BM, 1), blk, SMEM_BYTES>>>(Wsg, nullptr);
    mma_kernel<1><<<dim3(DF/BN, TTOT/BM, 1), blk, SMEM_BYTES>>>(Wsu, nullptr);
    mma_kernel<2><<<dim3(DM/BN, TTOT/BM, 1), blk, SMEM_BYTES>>>(Wsd, out);

    // routed experts
    mma_kernel<3><<<dim3(DF/BN, TPE/BM, NEXP), blk, SMEM_BYTES>>>(Weg, nullptr);
    mma_kernel<4><<<dim3(DF/BN, TPE/BM, NEXP), blk, SMEM_BYTES>>>(Weu, nullptr);
    mma_kernel<5><<<dim3(DM/BN, TPE/BM, NEXP), blk, SMEM_BYTES>>>(Wed, out);
}

// round 5
// speedup vs baseline: 2.4575x; 1.0357x over previous
#include <cuda_runtime.h>
#include <cstdint>

#define NEXP 16
#define TTOT 8192
#define DM   1024
#define DF   2048
#define TPE  TTOT

#define BM   128
#define BKC  32
#define AST  36                    // A smem row stride (floats), conflict-free
#define ASZ  (BM*AST)              // 4608 floats

// GU kernel: BN=128 for G and for U
#define BSTG 136
#define BSZG (BKC*BSTG)            // 4352 floats
#define STG_GU (ASZ + 2*BSZG)      // 13312 floats
#define SMEM_GU (2*STG_GU*4)       // 106496 B

// Down kernel: BN=256
#define BSTD 264
#define BSZD (BKC*BSTD)            // 8448 floats
#define STG_DN (ASZ + BSZD)        // 13056 floats
#define SMEM_DN (2*STG_DN*4)       // 104448 B

// ---------------- device scratch ----------------
__device__ int   g_cnt[NEXP];
__device__ int   g_off[NEXP];
__device__ int   g_tok[NEXP*TPE];
__device__ float g_wt [NEXP*TPE];
__device__ float g_Xr [(size_t)TTOT*DM];
__device__ float g_ACT[(size_t)3*TTOT*DF];   // dense rows [0,T), routed rows [T,3T)

// ---------------- helpers ----------------
__device__ __forceinline__ float tf32rnd(float v){
    uint32_t o; asm("cvt.rna.tf32.f32 %0, %1;" : "=r"(o) : "f"(v));
    return __uint_as_float(o);
}
__device__ __forceinline__ void cp_async16(uint32_t saddr, const void* g, int sz){
    asm volatile("cp.async.ca.shared.global [%0], [%1], 16, %2;\n" :: "r"(saddr), "l"(g), "r"(sz) : "memory");
}
__device__ __forceinline__ void cp_commit(){ asm volatile("cp.async.commit_group;\n" ::: "memory"); }
__device__ __forceinline__ void cp_wait1(){ asm volatile("cp.async.wait_group 1;\n" ::: "memory"); }
__device__ __forceinline__ void cp_wait0(){ asm volatile("cp.async.wait_group 0;\n" ::: "memory"); }
__device__ __forceinline__ uint32_t smem_u32(const void* p){
    uint32_t a;
    asm("{ .reg .u64 t; cvta.to.shared.u64 t, %1; cvt.u32.u64 %0, t; }" : "=r"(a) : "l"(p));
    return a;
}
__device__ __forceinline__ void mma_tf32(float c[4], uint32_t a0, uint32_t a1, uint32_t a2, uint32_t a3,
                                         uint32_t b0, uint32_t b1){
    asm volatile("mma.sync.aligned.m16n8k8.row.col.f32.tf32.tf32.f32 "
                 "{%0,%1,%2,%3}, {%4,%5,%6,%7}, {%8,%9}, {%0,%1,%2,%3};"
                 : "+f"(c[0]), "+f"(c[1]), "+f"(c[2]), "+f"(c[3])
                 : "r"(a0), "r"(a1), "r"(a2), "r"(a3), "r"(b0), "r"(b1));
}

// ---------------- small kernels ----------------
__global__ void zero_cnt_kernel(){ if (threadIdx.x < NEXP) g_cnt[threadIdx.x] = 0; }

__global__ void scan_kernel(){
    if (threadIdx.x == 0){
        int s = 0;
        #pragma unroll
        for (int e = 0; e < NEXP; e++){ g_off[e] = s; s += g_cnt[e]; }
    }
}

__global__ void roundx_kernel(const float* __restrict__ x){
    int i = blockIdx.x*blockDim.x + threadIdx.x;
    float4 v = reinterpret_cast<const float4*>(x)[i];
    v.x = tf32rnd(v.x); v.y = tf32rnd(v.y); v.z = tf32rnd(v.z); v.w = tf32rnd(v.w);
    reinterpret_cast<float4*>(g_Xr)[i] = v;
}

__global__ void router_kernel(const float* __restrict__ x, const float* __restrict__ Wr){
    int gw   = (blockIdx.x*blockDim.x + threadIdx.x) >> 5;
    int lane = threadIdx.x & 31;
    if (gw >= TTOT) return;
    const float* xr = x + (size_t)gw * DM;
    float acc[NEXP];
    #pragma unroll
    for (int e = 0; e < NEXP; e++) acc[e] = 0.f;
    for (int d = lane; d < DM; d += 32){
        float xv = xr[d];
        const float4* wr = reinterpret_cast<const float4*>(Wr + d*NEXP);
        #pragma unroll
        for (int q = 0; q < 4; q++){
            float4 w = wr[q];
            acc[4*q+0] = fmaf(xv, w.x, acc[4*q+0]);
            acc[4*q+1] = fmaf(xv, w.y, acc[4*q+1]);
            acc[4*q+2] = fmaf(xv, w.z, acc[4*q+2]);
            acc[4*q+3] = fmaf(xv, w.w, acc[4*q+3]);
        }
    }
    #pragma unroll
    for (int e = 0; e < NEXP; e++){
        #pragma unroll
        for (int o = 16; o > 0; o >>= 1) acc[e] += __shfl_xor_sync(0xffffffffu, acc[e], o);
    }
    if (lane == 0){
        float mx = acc[0];
        #pragma unroll
        for (int e = 1; e < NEXP; e++) mx = fmaxf(mx, acc[e]);
        float p[NEXP];
        #pragma unroll
        for (int e = 0; e < NEXP; e++) p[e] = __expf(acc[e] - mx);
        float b1 = -1.f, b2 = -1.f; int i1 = 0, i2 = 0;
        #pragma unroll
        for (int e = 0; e < NEXP; e++){
            float v = p[e];
            if (v > b1){ b2 = b1; i2 = i1; b1 = v; i1 = e; }
            else if (v > b2){ b2 = v; i2 = e; }
        }
        float inv = 1.f / (b1 + b2);
        int p1 = atomicAdd(&g_cnt[i1], 1);
        g_tok[i1*TPE + p1] = gw;  g_wt[i1*TPE + p1] = b1 * inv;
        int p2 = atomicAdd(&g_cnt[i2], 1);
        g_tok[i2*TPE + p2] = gw;  g_wt[i2*TPE + p2] = b2 * inv;
    }
}

// ---------------- fused gate+up GEMM ----------------
// z=0: dense shared expert (A = g_Xr rows, M=TTOT) -> g_ACT rows [0,T)
// z=1..16: routed expert e=z-1 (A = gathered g_Xr) -> g_ACT rows [T+off, ...)
// Each warp holds G and U accumulators for the same 64x32 tile -> silu fused.
__global__ void __launch_bounds__(256)
gu_kernel(const float* __restrict__ Wsg, const float* __restrict__ Wsu,
          const float* __restrict__ Weg, const float* __restrict__ Weu)
{
    constexpr int KT = DM / BKC;   // 32
    extern __shared__ float sm[];

    const int z = blockIdx.z;
    const bool routed = (z > 0);
    const int e = z - 1;
    const int M = routed ? g_cnt[e] : TTOT;
    const int m0 = blockIdx.y * BM;
    if (m0 >= M) return;
    const int n0 = blockIdx.x * 128;

    const float* Bg = routed ? Weg + (size_t)e*DM*DF : Wsg;
    const float* Bu = routed ? Weu + (size_t)e*DM*DF : Wsu;
    const int abase = routed ? (TTOT + g_off[e]) : 0;

    const int tid = threadIdx.x;
    const int rb  = tid >> 3;
    const int cfa = (tid & 7) * 4;
    const float* arow[4]; int asz[4];
    #pragma unroll
    for (int p = 0; p < 4; p++){
        int gm = m0 + rb + p*32;
        if (routed){
            int ok = gm < M;
            arow[p] = g_Xr + (size_t)(ok ? g_tok[e*TPE + gm] : 0) * DM;
            asz[p]  = ok ? 16 : 0;
        } else {
            arow[p] = g_Xr + (size_t)gm * DM;
            asz[p]  = 16;
        }
    }
    const int rb2 = tid >> 5;
    const int cfb = (tid & 31) * 4;
    const uint32_t smb = smem_u32(sm);

    auto load_chunk = [&](int kt, int s){
        const int k0 = kt * BKC;
        const uint32_t sb = smb + (uint32_t)(s*STG_GU*4);
        #pragma unroll
        for (int p = 0; p < 4; p++)
            cp_async16(sb + (uint32_t)(((rb + p*32)*AST + cfa)*4), arow[p] + k0 + cfa, asz[p]);
        #pragma unroll
        for (int p = 0; p < 4; p++){
            int r = rb2 + p*8;
            cp_async16(sb + (uint32_t)((ASZ + r*BSTG + cfb)*4),
                       Bg + (size_t)(k0 + r)*DF + n0 + cfb, 16);
            cp_async16(sb + (uint32_t)((ASZ + BSZG + r*BSTG + cfb)*4),
                       Bu + (size_t)(k0 + r)*DF + n0 + cfb, 16);
        }
    };
    auto round_B = [&](int s){
        float* B0 = sm + s*STG_GU + ASZ;
        #pragma unroll
        for (int p = 0; p < 4; p++){
            float4* q1 = reinterpret_cast<float4*>(B0 + (rb2 + p*8)*BSTG + cfb);
            float4* q2 = reinterpret_cast<float4*>(B0 + BSZG + (rb2 + p*8)*BSTG + cfb);
            float4 v1 = *q1, v2 = *q2;
            v1.x=tf32rnd(v1.x); v1.y=tf32rnd(v1.y); v1.z=tf32rnd(v1.z); v1.w=tf32rnd(v1.w);
            v2.x=tf32rnd(v2.x); v2.y=tf32rnd(v2.y); v2.z=tf32rnd(v2.z); v2.w=tf32rnd(v2.w);
            *q1 = v1; *q2 = v2;
        }
    };

    const int wid = tid >> 5, lane = tid & 31;
    const int g = lane >> 2, t = lane & 3;
    const int wm = wid & 1;
    const int wn = wid >> 1;

    float cg[4][4][4], cu[4][4][4];
    #pragma unroll
    for (int i = 0; i < 4; i++)
        #pragma unroll
        for (int j = 0; j < 4; j++)
            #pragma unroll
            for (int q = 0; q < 4; q++){ cg[i][j][q] = 0.f; cu[i][j][q] = 0.f; }

    load_chunk(0, 0); cp_commit();

    for (int kt = 0; kt < KT; kt++){
        const int s = kt & 1;
        if (kt + 1 < KT){ load_chunk(kt+1, s^1); cp_commit(); cp_wait1(); }
        else            { cp_wait0(); }
        round_B(s);
        __syncthreads();

        const float* As0 = sm + s*STG_GU;
        const float* ab  = As0 + (wm*64 + g)*AST + t;
        const float* bgb = As0 + ASZ + t*BSTG + wn*32 + g;
        const float* bub = bgb + BSZG;

        #pragma unroll
        for (int kk = 0; kk < BKC; kk += 8){
            uint32_t a[4][4], bg[4][2], bu[4][2];
            #pragma unroll
            for (int i = 0; i < 4; i++){
                a[i][0] = __float_as_uint(ab[(i*16    )*AST + kk    ]);
                a[i][1] = __float_as_uint(ab[(i*16 + 8)*AST + kk    ]);
                a[i][2] = __float_as_uint(ab[(i*16    )*AST + kk + 4]);
                a[i][3] = __float_as_uint(ab[(i*16 + 8)*AST + kk + 4]);
            }
            #pragma unroll
            for (int j = 0; j < 4; j++){
                bg[j][0] = __float_as_uint(bgb[(kk    )*BSTG + j*8]);
                bg[j][1] = __float_as_uint(bgb[(kk + 4)*BSTG + j*8]);
                bu[j][0] = __float_as_uint(bub[(kk    )*BSTG + j*8]);
                bu[j][1] = __float_as_uint(bub[(kk + 4)*BSTG + j*8]);
            }
            #pragma unroll
            for (int i = 0; i < 4; i++)
                #pragma unroll
                for (int j = 0; j < 4; j++){
                    mma_tf32(cg[i][j], a[i][0], a[i][1], a[i][2], a[i][3], bg[j][0], bg[j][1]);
                    mma_tf32(cu[i][j], a[i][0], a[i][1], a[i][2], a[i][3], bu[j][0], bu[j][1]);
                }
        }
        __syncthreads();
    }

    // epilogue: act = tf32rnd( silu(G) * U )
    #pragma unroll
    for (int i = 0; i < 4; i++){
        #pragma unroll
        for (int h = 0; h < 2; h++){
            const int gm = m0 + wm*64 + i*16 + g + h*8;
            if (routed && gm >= M) continue;
            float* drow = g_ACT + (size_t)(abase + gm)*DF;
            #pragma unroll
            for (int j = 0; j < 4; j++){
                const int cc = n0 + wn*32 + j*8 + 2*t;
                float g0 = cg[i][j][2*h], g1 = cg[i][j][2*h+1];
                float u0 = cu[i][j][2*h], u1 = cu[i][j][2*h+1];
                float o0 = tf32rnd(u0 * (g0 / (1.f + __expf(-g0))));
                float o1 = tf32rnd(u1 * (g1 / (1.f + __expf(-g1))));
                *reinterpret_cast<float2*>(drow + cc) = make_float2(o0, o1);
            }
        }
    }
}

// ---------------- down GEMM (BN=256, warp tile 64x64) ----------------
// ROUTED=0: A = g_ACT rows [0,T), plain store to Out
// ROUTED=1: A = g_ACT rows [T+off..), Out += w * C (atomic)
template<int ROUTED>
__global__ void __launch_bounds__(256)
down_kernel(const float* __restrict__ Wsd, const float* __restrict__ Wed, float* __restrict__ Out)
{
    constexpr int KT = DF / BKC;   // 64
    extern __shared__ float sm[];

    const int e  = ROUTED ? blockIdx.z : 0;
    const int M  = ROUTED ? g_cnt[e] : TTOT;
    const int m0 = blockIdx.y * BM;
    if (m0 >= M) return;
    const int n0 = blockIdx.x * 256;

    const float* B = ROUTED ? Wed + (size_t)e*DF*DM : Wsd;
    const int offe = ROUTED ? g_off[e] : 0;
    const float* A = g_ACT + (size_t)(ROUTED ? (TTOT + offe) : 0) * DF;

    const int tid = threadIdx.x;
    const int rb  = tid >> 3;
    const int cfa = (tid & 7) * 4;
    const float* arow[4]; int asz[4];
    #pragma unroll
    for (int p = 0; p < 4; p++){
        int gm = m0 + rb + p*32;
        int ok = (!ROUTED) || (gm < M);
        arow[p] = A + (size_t)(ok ? gm : 0) * DF;
        asz[p]  = ok ? 16 : 0;
    }
    const int rb2 = tid >> 5;
    const int cfb = (tid & 31) * 4;
    const uint32_t smb = smem_u32(sm);

    auto load_chunk = [&](int kt, int s){
        const int k0 = kt * BKC;
        const uint32_t sb = smb + (uint32_t)(s*STG_DN*4);
        #pragma unroll
        for (int p = 0; p < 4; p++)
            cp_async16(sb + (uint32_t)(((rb + p*32)*AST + cfa)*4), arow[p] + k0 + cfa, asz[p]);
        #pragma unroll
        for (int p = 0; p < 4; p++){
            int r = rb2 + p*8;
            cp_async16(sb + (uint32_t)((ASZ + r*BSTD + cfb)*4),
                       B + (size_t)(k0 + r)*DM + n0 + cfb, 16);
            cp_async16(sb + (uint32_t)((ASZ + r*BSTD + cfb + 128)*4),
                       B + (size_t)(k0 + r)*DM + n0 + cfb + 128, 16);
        }
    };
    auto round_B = [&](int s){
        float* B0 = sm + s*STG_DN + ASZ;
        #pragma unroll
        for (int p = 0; p < 4; p++){
            float4* q1 = reinterpret_cast<float4*>(B0 + (rb2 + p*8)*BSTD + cfb);
            float4* q2 = reinterpret_cast<float4*>(B0 + (rb2 + p*8)*BSTD + cfb + 128);
            float4 v1 = *q1, v2 = *q2;
            v1.x=tf32rnd(v1.x); v1.y=tf32rnd(v1.y); v1.z=tf32rnd(v1.z); v1.w=tf32rnd(v1.w);
            v2.x=tf32rnd(v2.x); v2.y=tf32rnd(v2.y); v2.z=tf32rnd(v2.z); v2.w=tf32rnd(v2.w);
            *q1 = v1; *q2 = v2;
        }
    };

    const int wid = tid >> 5, lane = tid & 31;
    const int g = lane >> 2, t = lane & 3;
    const int wm = wid & 1;
    const int wn = wid >> 1;   // 0..3, 64 cols each

    float c[4][8][4];
    #pragma unroll
    for (int i = 0; i < 4; i++)
        #pragma unroll
        for (int j = 0; j < 8; j++)
            #pragma unroll
            for (int q = 0; q < 4; q++) c[i][j][q] = 0.f;

    load_chunk(0, 0); cp_commit();

    for (int kt = 0; kt < KT; kt++){
        const int s = kt & 1;
        if (kt + 1 < KT){ load_chunk(kt+1, s^1); cp_commit(); cp_wait1(); }
        else            { cp_wait0(); }
        round_B(s);
        __syncthreads();

        const float* As0 = sm + s*STG_DN;
        const float* ab  = As0 + (wm*64 + g)*AST + t;
        const float* bb  = As0 + ASZ + t*BSTD + wn*64 + g;

        #pragma unroll
        for (int kk = 0; kk < BKC; kk += 8){
            uint32_t a[4][4], b[8][2];
            #pragma unroll
            for (int i = 0; i < 4; i++){
                a[i][0] = __float_as_uint(ab[(i*16    )*AST + kk    ]);
                a[i][1] = __float_as_uint(ab[(i*16 + 8)*AST + kk    ]);
                a[i][2] = __float_as_uint(ab[(i*16    )*AST + kk + 4]);
                a[i][3] = __float_as_uint(ab[(i*16 + 8)*AST + kk + 4]);
            }
            #pragma unroll
            for (int j = 0; j < 8; j++){
                b[j][0] = __float_as_uint(bb[(kk    )*BSTD + j*8]);
                b[j][1] = __float_as_uint(bb[(kk + 4)*BSTD + j*8]);
            }
            #pragma unroll
            for (int i = 0; i < 4; i++)
                #pragma unroll
                for (int j = 0; j < 8; j++)
                    mma_tf32(c[i][j], a[i][0], a[i][1], a[i][2], a[i][3], b[j][0], b[j][1]);
        }
        __syncthreads();
    }

    #pragma unroll
    for (int i = 0; i < 4; i++){
        #pragma unroll
        for (int h = 0; h < 2; h++){
            const int gm = m0 + wm*64 + i*16 + g + h*8;
            if (ROUTED && gm >= M) continue;
            int tok = gm; float w = 1.f;
            if (ROUTED){ tok = g_tok[e*TPE + gm]; w = g_wt[e*TPE + gm]; }
            float* orow = Out + (size_t)tok*DM;
            #pragma unroll
            for (int j = 0; j < 8; j++){
                const int cc = n0 + wn*64 + j*8 + 2*t;
                const float v0 = c[i][j][2*h], v1 = c[i][j][2*h+1];
                if (!ROUTED){
                    *reinterpret_cast<float2*>(orow + cc) = make_float2(v0, v1);
                } else {
                    atomicAdd(orow + cc + 0, w * v0);
                    atomicAdd(orow + cc + 1, w * v1);
                }
            }
        }
    }
}

// ---------------- launch ----------------
extern "C" void kernel_launch(void* const* d_in, const int* in_sizes, int n_in,
                              void* d_out, int out_size)
{
    const float* x   = (const float*)d_in[0];
    const float* Wr  = (const float*)d_in[1];
    const float* Wsg = (const float*)d_in[2];
    const float* Wsu = (const float*)d_in[3];
    const float* Wsd = (const float*)d_in[4];
    const float* Weg = (const float*)d_in[5];
    const float* Weu = (const float*)d_in[6];
    const float* Wed = (const float*)d_in[7];
    float* out = (float*)d_out;

    cudaFuncSetAttribute(gu_kernel,      cudaFuncAttributeMaxDynamicSharedMemorySize, SMEM_GU);
    cudaFuncSetAttribute(down_kernel<0>, cudaFuncAttributeMaxDynamicSharedMemorySize, SMEM_DN);
    cudaFuncSetAttribute(down_kernel<1>, cudaFuncAttributeMaxDynamicSharedMemorySize, SMEM_DN);

    zero_cnt_kernel<<<1, 32>>>();
    router_kernel<<<TTOT/8, 256>>>(x, Wr);
    scan_kernel<<<1, 32>>>();
    roundx_kernel<<<(TTOT*DM/4)/256, 256>>>(x);

    dim3 blk(256);
    // fused gate+up: z=0 shared dense, z=1..16 routed experts
    gu_kernel<<<dim3(DF/128, TTOT/BM, NEXP+1), blk, SMEM_GU>>>(Wsg, Wsu, Weg, Weu);
    // down: dense store, then routed atomic accumulate
    down_kernel<0><<<dim3(DM/256, TTOT/BM, 1),   blk, SMEM_DN>>>(Wsd, Wed, out);
    down_kernel<1><<<dim3(DM/256, TPE/BM, NEXP), blk, SMEM_DN>>>(Wsd, Wed, out);
}